// round 1
// baseline (speedup 1.0000x reference)
#include <cuda_runtime.h>

// SlowNorm: per-irrep L2 norms.
// irreps: (256,1) (256,3) (128,5) (64,7)  -> DIM=2112 in, OUT=704 out per row.
// Layout offsets (floats): scalars [0,256), l1 [256,1024), l2 [1024,1664), l3 [1664,2112).
// Output offsets: [0,256) |x| ; [256,512) d=3 ; [512,640) d=5 ; [640,704) d=7.

#define DIM      2112
#define OUT_DIM  704
#define THREADS  256

__global__ __launch_bounds__(THREADS) void slownorm_kernel(
    const float* __restrict__ in, float* __restrict__ out)
{
    __shared__ float s[DIM];

    const long long row = blockIdx.x;
    const float4* __restrict__ inrow =
        reinterpret_cast<const float4*>(in + row * (long long)DIM);
    float4* s4 = reinterpret_cast<float4*>(s);

    // Coalesced stage: 2112 floats = 528 float4; 256 threads -> 2-3 each.
    #pragma unroll
    for (int i = threadIdx.x; i < DIM / 4; i += THREADS)
        s4[i] = inrow[i];
    __syncthreads();

    float* __restrict__ orow = out + row * (long long)OUT_DIM;

    #pragma unroll
    for (int o = threadIdx.x; o < OUT_DIM; o += THREADS) {
        float v;
        if (o < 256) {
            // d=1: sqrt(x^2) == |x|
            v = fabsf(s[o]);
        } else if (o < 512) {
            const int b = 256 + (o - 256) * 3;
            float acc = s[b] * s[b];
            acc = fmaf(s[b + 1], s[b + 1], acc);
            acc = fmaf(s[b + 2], s[b + 2], acc);
            v = sqrtf(acc);
        } else if (o < 640) {
            const int b = 1024 + (o - 512) * 5;
            float acc = s[b] * s[b];
            #pragma unroll
            for (int j = 1; j < 5; j++) acc = fmaf(s[b + j], s[b + j], acc);
            v = sqrtf(acc);
        } else {
            const int b = 1664 + (o - 640) * 7;
            float acc = s[b] * s[b];
            #pragma unroll
            for (int j = 1; j < 7; j++) acc = fmaf(s[b + j], s[b + j], acc);
            v = sqrtf(acc);
        }
        orow[o] = v;
    }
}

extern "C" void kernel_launch(void* const* d_in, const int* in_sizes, int n_in,
                              void* d_out, int out_size)
{
    const float* features = (const float*)d_in[0];
    float* out = (float*)d_out;
    const int batch = in_sizes[0] / DIM;   // 65536
    slownorm_kernel<<<batch, THREADS>>>(features, out);
}